// round 5
// baseline (speedup 1.0000x reference)
#include <cuda_runtime.h>

#define NB   16
#define NH   32
#define HD   64
#define TT   8192
#define NX   2048
#define TC   1024              // t-chunk per CTA
#define NCHUNK (TT / TC)       // 8
#define THREADS 256

// ---- Prologue: out[bh][d] = (q.k) * v[d]  (independent of past_k/past_v) ----
__global__ __launch_bounds__(256)
void attn_prologue_kernel(const float* __restrict__ q,
                          const float* __restrict__ k,
                          const float* __restrict__ v,
                          float* __restrict__ out)
{
    const int g   = threadIdx.x >> 6;              // 0..3 (bh within block)
    const int d   = threadIdx.x & 63;
    const int bh  = blockIdx.x * 4 + g;            // 128 blocks * 4 = 512
    const size_t base = (size_t)bh * HD;           // == b*NX + h*HD

    __shared__ float prod[4][HD];

    const float qd = q[base + d];
    const float kd = k[base + d];
    const float vd = v[base + d];
    prod[g][d] = qd * kd;
    __syncthreads();

    float wc = 0.f;
    #pragma unroll
    for (int i = 0; i < HD; i++) wc += prod[g][i];  // same order for all -> deterministic

    out[base + d] = wc * vd;
}

// ---- Main: each CTA streams one (bh, t-chunk) and REDG-adds its partial ----
__global__ __launch_bounds__(THREADS, 4)
void attn_chunk_kernel(const float* __restrict__ q,
                       const float* __restrict__ past_k,
                       const float* __restrict__ past_v,
                       float* __restrict__ out)
{
    const int chunk = blockIdx.x;      // 0..7
    const int bh    = blockIdx.y;      // 0..511
    const int tid   = threadIdx.x;

    __shared__ float qs[HD];
    __shared__ float w[TC];            // 4 KB
    __shared__ float red[16 * HD];     // 4 KB

    if (tid < HD)
        qs[tid] = q[(size_t)bh * HD + tid];
    __syncthreads();

    // ---- Phase A: w[t] = sum_d q[d] * K[d, t] over this chunk ----
    // past_k: [B,H,HD,T], contiguous in t
    const float* Kp = past_k + (size_t)bh * HD * TT + (size_t)chunk * TC;
    {
        const int t = tid * 4;         // 256 threads * 4 = 1024 = TC
        float4 acc = make_float4(0.f, 0.f, 0.f, 0.f);
        #pragma unroll 16
        for (int d = 0; d < HD; d++) {
            const float4 kk = __ldcs(reinterpret_cast<const float4*>(Kp + (size_t)d * TT + t));
            const float qd = qs[d];
            acc.x = fmaf(qd, kk.x, acc.x);
            acc.y = fmaf(qd, kk.y, acc.y);
            acc.z = fmaf(qd, kk.z, acc.z);
            acc.w = fmaf(qd, kk.w, acc.w);
        }
        *reinterpret_cast<float4*>(&w[t]) = acc;
    }
    __syncthreads();

    // ---- Phase B: partial[d] = sum_{t in chunk} w[t] * V[t, d] ----
    // past_v: [B,H,T,HD], contiguous in d (256B rows)
    const float* Vp = past_v + (size_t)bh * TT * HD + (size_t)chunk * TC * HD;
    const int dg = tid & 15;           // float4 index along d
    const int tg = tid >> 4;           // t-stride group

    float4 acc = make_float4(0.f, 0.f, 0.f, 0.f);
    #pragma unroll 8
    for (int t = tg; t < TC; t += 16) {
        const float  wt = w[t];
        const float4 vv = __ldcs(reinterpret_cast<const float4*>(Vp + (size_t)t * HD + dg * 4));
        acc.x = fmaf(wt, vv.x, acc.x);
        acc.y = fmaf(wt, vv.y, acc.y);
        acc.z = fmaf(wt, vv.z, acc.z);
        acc.w = fmaf(wt, vv.w, acc.w);
    }
    *reinterpret_cast<float4*>(&red[tg * HD + dg * 4]) = acc;
    __syncthreads();

    // ---- Final: 64 REDG.ADD per CTA straight into out ----
    if (tid < HD) {
        float s = 0.f;
        #pragma unroll
        for (int g = 0; g < 16; g++) s += red[g * HD + tid];
        atomicAdd(&out[(size_t)bh * HD + tid], s);
    }
}

extern "C" void kernel_launch(void* const* d_in, const int* in_sizes, int n_in,
                              void* d_out, int out_size)
{
    const float* q      = (const float*)d_in[0];
    const float* k      = (const float*)d_in[1];
    const float* v      = (const float*)d_in[2];
    const float* past_k = (const float*)d_in[3];
    const float* past_v = (const float*)d_in[4];
    float* out          = (float*)d_out;

    attn_prologue_kernel<<<NB * NH / 4, 256>>>(q, k, v, out);

    dim3 grid(NCHUNK, NB * NH);
    attn_chunk_kernel<<<grid, THREADS>>>(q, past_k, past_v, out);
}